// round 10
// baseline (speedup 1.0000x reference)
#include <cuda_runtime.h>

// FuzzyPooling, TF-faithful flat-group semantics.
// x: [4,384,384,48] f32  ->  out: [4,128,128,48] f32
// Each output (b,r,c,g) uses 9 consecutive "depth" values d = 9g..9g+8 of the
// 432-float flattened 3x3 patch (depth order: (kr,kc,channel)).
// For fixed (b,r) and 16 consecutive output columns, the data is 3 rows of
// 2304 contiguous floats -> staged in shared memory with coalesced float4 loads.

#define TILE_CC 16
#define THREADS 256
#define N_POS_FLOATS 432              // 9*48 floats per output position
#define ROW_FLOATS   (TILE_CC * 144)  // 2304 contiguous floats per patch-row
#define EPSF 1e-4f
#define NEG_HALF_LOG2E (-0.7213475204444817f)

__device__ __forceinline__ float ex2a(float x) {
    float y; asm("ex2.approx.f32 %0, %1;" : "=f"(y) : "f"(x)); return y;
}
__device__ __forceinline__ float rcpa(float x) {
    float y; asm("rcp.approx.f32 %0, %1;" : "=f"(y) : "f"(x)); return y;
}

__global__ __launch_bounds__(THREADS)
void fuzzy_pool_kernel(const float* __restrict__ x, float* __restrict__ out)
{
    // sm[p*432 + d] = patch value at depth d for local output position p
    __shared__ float sm[TILE_CC * N_POS_FLOATS];   // 27648 B

    const int cc0 = blockIdx.x * TILE_CC;   // output column tile start (0..127)
    const int r   = blockIdx.y;             // output row (0..127)
    const int bb  = blockIdx.z;             // batch (0..3)
    const int tid = threadIdx.x;

    const int row_stride = 384 * 48;                         // floats per input row
    const float* base = x + ((bb * 384 + 3 * r) * 384 + 3 * cc0) * 48;

    // ---- Stage: 3 rows x 2304 floats, float4-coalesced, swizzled so each
    //      position's 432 depth floats are contiguous in smem.
    for (int i = tid; i < 3 * (ROW_FLOATS / 4); i += THREADS) {
        int kr  = i / (ROW_FLOATS / 4);          // 0..2
        int j4  = i - kr * (ROW_FLOATS / 4);     // float4 index within row seg
        float4 v = *(const float4*)(base + kr * row_stride + j4 * 4);
        int p    = j4 / 36;                      // local position 0..15
        int rem4 = j4 - p * 36;                  // float4 offset within 144-chunk
        *(float4*)(&sm[p * N_POS_FLOATS + kr * 144 + rem4 * 4]) = v;
    }
    __syncthreads();

    const int out_base = ((bb * 128 + r) * 128 + cc0) * 48;

    for (int o = tid; o < TILE_CC * 48; o += THREADS) {
        int p = o / 48;
        int g = o - p * 48;
        const float* xs = &sm[p * N_POS_FLOATS + g * 9];

        float xv[9];
        #pragma unroll
        for (int t = 0; t < 9; t++) xv[t] = xs[t];

        // --- memberships kmm[5] = [m(1:8), m(2:7), m(3:6), x4, m(0:9)]
        float s3 = xv[3] + xv[4] + xv[5];
        float s2 = s3 + xv[2] + xv[6];
        float s1 = s2 + xv[1] + xv[7];
        float s0 = s1 + xv[0] + xv[8];
        float km[5];
        km[0] = s1 * (1.0f / 7.0f);
        km[1] = s2 * (1.0f / 5.0f);
        km[2] = s3 * (1.0f / 3.0f);
        km[3] = xv[4];
        km[4] = s0 * (1.0f / 9.0f);

        float v_avg = (km[0] + km[1] + km[2] + km[3] + km[4]) * 0.2f;

        // --- omega & var
        float om[9];
        #pragma unroll
        for (int t = 0; t < 9; t++) om[t] = fabsf(xv[t] - v_avg);
        float u3 = om[3] + om[4] + om[5];
        float u2 = u3 + om[2] + om[6];
        float u1 = u2 + om[1] + om[7];
        float u0 = u1 + om[0] + om[8];
        float var4 = u0 * (1.0f / 9.0f) + EPSF;
        float var[5];
        var[0] = u1 * (1.0f / 7.0f) + EPSF;
        var[1] = u2 * (1.0f / 5.0f) + EPSF;
        var[2] = u3 * (1.0f / 3.0f) + EPSF;
        var[3] = om[4] + EPSF;
        var[4] = var4;

        // c_j = -0.5*log2(e)/var_j  (exp(-0.5 d^2/var) == exp2(d^2 * c))
        float cj[5];
        #pragma unroll
        for (int j = 0; j < 5; j++) cj[j] = NEG_HALF_LOG2E * rcpa(var[j]);

        // --- pi table: per-t sum over j of exp2(e), and max exponent over j
        float sump[9], emax[9];
        #pragma unroll
        for (int t = 0; t < 9; t++) {
            float d0 = xv[t] - km[0];
            float e0 = d0 * d0 * cj[0];
            emax[t]  = e0;
            sump[t]  = ex2a(e0);
            #pragma unroll
            for (int j = 1; j < 5; j++) {
                float d = xv[t] - km[j];
                float e = d * d * cj[j];
                emax[t] = fmaxf(emax[t], e);
                sump[t] += ex2a(e);
            }
        }

        // thresh = min_t max_j pi = exp2(min_t max_j e)   (exp2 monotone)
        float te = emax[0];
        #pragma unroll
        for (int t = 1; t < 9; t++) te = fminf(te, emax[t]);
        float thresh = ex2a(te);

        // any(avg_pi > thresh)  <=>  max_t(sump_t/5) > thresh
        float mx = sump[0];
        #pragma unroll
        for (int t = 1; t < 9; t++) mx = fmaxf(mx, sump[t]);
        bool m_mem = (mx * 0.2f) > thresh;

        // denoised = sum(avg_pi*x)/sum(avg_pi)  (1/5 factor cancels)
        float num = 0.0f, den = 0.0f;
        #pragma unroll
        for (int t = 0; t < 9; t++) {
            num = fmaf(sump[t], xv[t], num);
            den += sump[t];
        }
        float denoised = num * rcpa(den);

        bool m_var = (var4 < EPSF);   // faithful to reference (effectively never)

        float pooled = m_mem ? km[4] : (m_var ? v_avg : denoised);
        out[out_base + o] = pooled;
    }
}

extern "C" void kernel_launch(void* const* d_in, const int* in_sizes, int n_in,
                              void* d_out, int out_size)
{
    const float* x = (const float*)d_in[0];
    float* out = (float*)d_out;
    dim3 grid(128 / TILE_CC, 128, 4);   // (cc tiles, R, B)
    fuzzy_pool_kernel<<<grid, THREADS>>>(x, out);
}

// round 12
// speedup vs baseline: 1.0038x; 1.0038x over previous
#include <cuda_runtime.h>

// FuzzyPooling, TF-faithful flat-group semantics.
// x: [4,384,384,48] f32  ->  out: [4,128,128,48] f32
// Each output (b,r,c,g) uses 9 consecutive "depth" values d = 9g..9g+8 of the
// 432-float flattened 3x3 patch (depth order: (kr,kc,channel)).
// For fixed (b,r) and 16 consecutive output columns, the data is 3 rows of
// 2304 contiguous floats -> staged in shared memory with coalesced float4 loads.

#define TILE_CC 16
#define THREADS 256
#define N_POS_FLOATS 432              // 9*48 floats per output position
#define ROW_FLOATS   (TILE_CC * 144)  // 2304 contiguous floats per patch-row
#define EPSF 1e-4f
#define NEG_HALF_LOG2E (-0.7213475204444817f)

__device__ __forceinline__ float ex2a(float x) {
    float y; asm("ex2.approx.f32 %0, %1;" : "=f"(y) : "f"(x)); return y;
}
__device__ __forceinline__ float rcpa(float x) {
    float y; asm("rcp.approx.f32 %0, %1;" : "=f"(y) : "f"(x)); return y;
}

__global__ __launch_bounds__(THREADS)
void fuzzy_pool_kernel(const float* __restrict__ x, float* __restrict__ out)
{
    // sm[p*432 + d] = patch value at depth d for local output position p
    __shared__ float sm[TILE_CC * N_POS_FLOATS];   // 27648 B

    const int cc0 = blockIdx.x * TILE_CC;   // output column tile start (0..127)
    const int r   = blockIdx.y;             // output row (0..127)
    const int bb  = blockIdx.z;             // batch (0..3)
    const int tid = threadIdx.x;

    const int row_stride = 384 * 48;                         // floats per input row
    const float* base = x + ((bb * 384 + 3 * r) * 384 + 3 * cc0) * 48;

    // ---- Stage: 3 rows x 2304 floats, float4-coalesced, swizzled so each
    //      position's 432 depth floats are contiguous in smem.
    for (int i = tid; i < 3 * (ROW_FLOATS / 4); i += THREADS) {
        int kr  = i / (ROW_FLOATS / 4);          // 0..2
        int j4  = i - kr * (ROW_FLOATS / 4);     // float4 index within row seg
        float4 v = *(const float4*)(base + kr * row_stride + j4 * 4);
        int p    = j4 / 36;                      // local position 0..15
        int rem4 = j4 - p * 36;                  // float4 offset within 144-chunk
        *(float4*)(&sm[p * N_POS_FLOATS + kr * 144 + rem4 * 4]) = v;
    }
    __syncthreads();

    const int out_base = ((bb * 128 + r) * 128 + cc0) * 48;

    for (int o = tid; o < TILE_CC * 48; o += THREADS) {
        int p = o / 48;
        int g = o - p * 48;
        const float* xs = &sm[p * N_POS_FLOATS + g * 9];

        float xv[9];
        #pragma unroll
        for (int t = 0; t < 9; t++) xv[t] = xs[t];

        // --- memberships kmm[5] = [m(1:8), m(2:7), m(3:6), x4, m(0:9)]
        float s3 = xv[3] + xv[4] + xv[5];
        float s2 = s3 + xv[2] + xv[6];
        float s1 = s2 + xv[1] + xv[7];
        float s0 = s1 + xv[0] + xv[8];
        float km[5];
        km[0] = s1 * (1.0f / 7.0f);
        km[1] = s2 * (1.0f / 5.0f);
        km[2] = s3 * (1.0f / 3.0f);
        km[3] = xv[4];
        km[4] = s0 * (1.0f / 9.0f);

        float v_avg = (km[0] + km[1] + km[2] + km[3] + km[4]) * 0.2f;

        // --- omega & var
        float om[9];
        #pragma unroll
        for (int t = 0; t < 9; t++) om[t] = fabsf(xv[t] - v_avg);
        float u3 = om[3] + om[4] + om[5];
        float u2 = u3 + om[2] + om[6];
        float u1 = u2 + om[1] + om[7];
        float u0 = u1 + om[0] + om[8];
        float var4 = u0 * (1.0f / 9.0f) + EPSF;
        float var[5];
        var[0] = u1 * (1.0f / 7.0f) + EPSF;
        var[1] = u2 * (1.0f / 5.0f) + EPSF;
        var[2] = u3 * (1.0f / 3.0f) + EPSF;
        var[3] = om[4] + EPSF;
        var[4] = var4;

        // c_j = -0.5*log2(e)/var_j  (exp(-0.5 d^2/var) == exp2(d^2 * c))
        float cj[5];
        #pragma unroll
        for (int j = 0; j < 5; j++) cj[j] = NEG_HALF_LOG2E * rcpa(var[j]);

        // --- pi table: per-t sum over j of exp2(e), and max exponent over j
        float sump[9], emax[9];
        #pragma unroll
        for (int t = 0; t < 9; t++) {
            float d0 = xv[t] - km[0];
            float e0 = d0 * d0 * cj[0];
            emax[t]  = e0;
            sump[t]  = ex2a(e0);
            #pragma unroll
            for (int j = 1; j < 5; j++) {
                float d = xv[t] - km[j];
                float e = d * d * cj[j];
                emax[t] = fmaxf(emax[t], e);
                sump[t] += ex2a(e);
            }
        }

        // thresh = min_t max_j pi = exp2(min_t max_j e)   (exp2 monotone)
        float te = emax[0];
        #pragma unroll
        for (int t = 1; t < 9; t++) te = fminf(te, emax[t]);
        float thresh = ex2a(te);

        // any(avg_pi > thresh)  <=>  max_t(sump_t/5) > thresh
        float mx = sump[0];
        #pragma unroll
        for (int t = 1; t < 9; t++) mx = fmaxf(mx, sump[t]);
        bool m_mem = (mx * 0.2f) > thresh;

        // denoised = sum(avg_pi*x)/sum(avg_pi)  (1/5 factor cancels)
        float num = 0.0f, den = 0.0f;
        #pragma unroll
        for (int t = 0; t < 9; t++) {
            num = fmaf(sump[t], xv[t], num);
            den += sump[t];
        }
        float denoised = num * rcpa(den);

        bool m_var = (var4 < EPSF);   // faithful to reference (effectively never)

        float pooled = m_mem ? km[4] : (m_var ? v_avg : denoised);
        out[out_base + o] = pooled;
    }
}

extern "C" void kernel_launch(void* const* d_in, const int* in_sizes, int n_in,
                              void* d_out, int out_size)
{
    const float* x = (const float*)d_in[0];
    float* out = (float*)d_out;
    dim3 grid(128 / TILE_CC, 128, 4);   // (cc tiles, R, B)
    fuzzy_pool_kernel<<<grid, THREADS>>>(x, out);
}